// round 8
// baseline (speedup 1.0000x reference)
#include <cuda_runtime.h>
#include <cuda_bf16.h>
#include <math_constants.h>

#define N_NODES 100000
#define N_EDGES 1600000
#define IN_CH   128
#define OUT_CH  64
#define NEG_SLOPE 0.2f
#define EPS_F 1e-10f

#define SCAN_BS 1024
#define NUM_SCAN_BLOCKS ((N_NODES + SCAN_BS - 1) / SCAN_BS)   // 98

// ---------------- scratch (no allocations allowed) ----------------
__device__ float g_h[(size_t)N_NODES * OUT_CH];   // 25.6 MB
__device__ float g_el[N_NODES];
__device__ float g_er[N_NODES];
__device__ int   g_deg[N_NODES];
__device__ int   g_fill[N_NODES];
__device__ int   g_rowptr[N_NODES + 1];
__device__ int   g_bsum[NUM_SCAN_BLOCKS];
__device__ int   g_src_sorted[N_EDGES];
__device__ float g_er_sorted[N_EDGES];

__device__ __forceinline__ float leaky(float v) {
    return v > 0.0f ? v : NEG_SLOPE * v;
}

// ---------------- K0: zero deg/fill ----------------
__global__ void init_kernel() {
    int i = blockIdx.x * blockDim.x + threadIdx.x;
    if (i < N_NODES) {
        g_deg[i]  = 0;
        g_fill[i] = 0;
    }
}

// ---------------- K1: h = x @ W^T  (+ fused e_l/e_r epilogue) ----------------
#define GEMM_ROWS 128
#define GEMM_KC   32
__global__ __launch_bounds__(128) void gemm_kernel(const float* __restrict__ x,
                                                   const float* __restrict__ W,
                                                   const float* __restrict__ a_l,
                                                   const float* __restrict__ a_r) {
    __shared__ float sw[GEMM_KC][OUT_CH];          // sw[k][oc]
    __shared__ float sx[GEMM_KC][GEMM_ROWS + 1];   // sx[k][row]

    int tid = threadIdx.x;
    int tx  = tid & 7;    // col group: cols tx*8 .. tx*8+7
    int ty  = tid >> 3;   // row group: rows ty*8 .. ty*8+7  (0..15)
    int row0 = blockIdx.x * GEMM_ROWS;

    float acc[8][8];
#pragma unroll
    for (int i = 0; i < 8; i++)
#pragma unroll
        for (int j = 0; j < 8; j++) acc[i][j] = 0.0f;

    for (int kc = 0; kc < IN_CH; kc += GEMM_KC) {
        for (int i = tid; i < GEMM_KC * OUT_CH; i += 128) {
            int oc = i >> 5;
            int k  = i & 31;
            sw[k][oc] = W[oc * IN_CH + kc + k];
        }
        for (int i = tid; i < GEMM_ROWS * GEMM_KC; i += 128) {
            int r = i >> 5;
            int k = i & 31;
            int row = row0 + r;
            sx[k][r] = (row < N_NODES) ? x[(size_t)row * IN_CH + kc + k] : 0.0f;
        }
        __syncthreads();

#pragma unroll
        for (int k = 0; k < GEMM_KC; k++) {
            float xv[8], wv[8];
#pragma unroll
            for (int i = 0; i < 8; i++) xv[i] = sx[k][ty * 8 + i];
#pragma unroll
            for (int j = 0; j < 8; j++) wv[j] = sw[k][tx * 8 + j];
#pragma unroll
            for (int i = 0; i < 8; i++)
#pragma unroll
                for (int j = 0; j < 8; j++)
                    acc[i][j] = fmaf(xv[i], wv[j], acc[i][j]);
        }
        __syncthreads();
    }

    // store h
#pragma unroll
    for (int i = 0; i < 8; i++) {
        int row = row0 + ty * 8 + i;
        if (row < N_NODES) {
            float4* dst = reinterpret_cast<float4*>(g_h + (size_t)row * OUT_CH + tx * 8);
            dst[0] = make_float4(acc[i][0], acc[i][1], acc[i][2], acc[i][3]);
            dst[1] = make_float4(acc[i][4], acc[i][5], acc[i][6], acc[i][7]);
        }
    }

    // fused e_l / e_r: the 8 threads (lanes) holding one row are consecutive.
    float al8[8], ar8[8];
#pragma unroll
    for (int j = 0; j < 8; j++) {
        al8[j] = a_l[tx * 8 + j];
        ar8[j] = a_r[tx * 8 + j];
    }
#pragma unroll
    for (int i = 0; i < 8; i++) {
        float sl = 0.0f, sr = 0.0f;
#pragma unroll
        for (int j = 0; j < 8; j++) {
            sl = fmaf(acc[i][j], al8[j], sl);
            sr = fmaf(acc[i][j], ar8[j], sr);
        }
#pragma unroll
        for (int m = 1; m < 8; m <<= 1) {
            sl += __shfl_xor_sync(0xFFFFFFFFu, sl, m);
            sr += __shfl_xor_sync(0xFFFFFFFFu, sr, m);
        }
        int row = row0 + ty * 8 + i;
        if (tx == 0 && row < N_NODES) {
            g_el[row] = sl;
            g_er[row] = sr;
        }
    }
}

// ---------------- K3: histogram of dst (4 edges/thread, int4) ----------------
__global__ void hist_kernel(const int* __restrict__ ei) {
    int t = blockIdx.x * blockDim.x + threadIdx.x;
    int e4 = t * 4;
    if (e4 >= N_EDGES) return;
    int4 d = *reinterpret_cast<const int4*>(ei + N_EDGES + e4);
    atomicAdd(&g_deg[d.x], 1);
    atomicAdd(&g_deg[d.y], 1);
    atomicAdd(&g_deg[d.z], 1);
    atomicAdd(&g_deg[d.w], 1);
}

// ---------------- K4a: per-block inclusive scan of deg ----------------
__global__ void scan_block_kernel() {
    __shared__ int warp_sums[32];
    int i = blockIdx.x * SCAN_BS + threadIdx.x;
    int lane = threadIdx.x & 31, wid = threadIdx.x >> 5;
    int v = (i < N_NODES) ? g_deg[i] : 0;
    int s = v;
#pragma unroll
    for (int o = 1; o < 32; o <<= 1) {
        int t = __shfl_up_sync(0xFFFFFFFFu, s, o);
        if (lane >= o) s += t;
    }
    if (lane == 31) warp_sums[wid] = s;
    __syncthreads();
    if (wid == 0) {
        int ws = warp_sums[lane];
#pragma unroll
        for (int o = 1; o < 32; o <<= 1) {
            int t = __shfl_up_sync(0xFFFFFFFFu, ws, o);
            if (lane >= o) ws += t;
        }
        warp_sums[lane] = ws;
    }
    __syncthreads();
    int incl = s + (wid > 0 ? warp_sums[wid - 1] : 0);
    if (i < N_NODES) g_rowptr[i + 1] = incl;
    if (threadIdx.x == SCAN_BS - 1) g_bsum[blockIdx.x] = incl;
}

// ---------------- K4b: exclusive scan of block sums (1 block) ----------------
__global__ void scan_bsum_kernel() {
    __shared__ int sh[NUM_SCAN_BLOCKS];
    int t = threadIdx.x;
    if (t < NUM_SCAN_BLOCKS) sh[t] = g_bsum[t];
    __syncthreads();
    if (t == 0) {
        int run = 0;
        for (int b = 0; b < NUM_SCAN_BLOCKS; b++) {
            int v = sh[b];
            sh[b] = run;
            run += v;
        }
    }
    __syncthreads();
    if (t < NUM_SCAN_BLOCKS) g_bsum[t] = sh[t];
}

// ---------------- K4c: add offsets ----------------
__global__ void scan_add_kernel() {
    int i = blockIdx.x * blockDim.x + threadIdx.x;
    if (i < N_NODES) g_rowptr[i + 1] += g_bsum[i >> 10];
    if (i == 0) g_rowptr[0] = 0;
}

// ---------------- K5: scatter src ids + er into CSR order (4 edges/thread) ----------------
__global__ void scatter_kernel(const int* __restrict__ ei) {
    int t = blockIdx.x * blockDim.x + threadIdx.x;
    int e4 = t * 4;
    if (e4 >= N_EDGES) return;
    int4 s = *reinterpret_cast<const int4*>(ei + e4);
    int4 d = *reinterpret_cast<const int4*>(ei + N_EDGES + e4);
#pragma unroll
    for (int j = 0; j < 4; j++) {
        int src = (j == 0) ? s.x : (j == 1) ? s.y : (j == 2) ? s.z : s.w;
        int dst = (j == 0) ? d.x : (j == 1) ? d.y : (j == 2) ? d.z : d.w;
        int pos = g_rowptr[dst] + atomicAdd(&g_fill[dst], 1);
        g_src_sorted[pos] = src;
        g_er_sorted[pos]  = g_er[src];
    }
}

// ---------------- K6: warp-per-node softmax + message gather (unroll x2) ----------------
// NOTE: max-shift dropped; differs from reference by eps*(e^max-1)/sum ~ 3e-8.
__global__ void msg_kernel(float* __restrict__ out, const float* __restrict__ bias) {
    int gtid = blockIdx.x * blockDim.x + threadIdx.x;
    int node = gtid >> 5;
    int lane = gtid & 31;
    if (node >= N_NODES) return;
    int p   = g_rowptr[node];
    int end = g_rowptr[node + 1];
    float el = g_el[node];
    float acc0 = 0.0f, acc1 = 0.0f, wsum = 0.0f;
    for (; p + 2 <= end; p += 2) {
        int   s0  = g_src_sorted[p];
        int   s1  = g_src_sorted[p + 1];
        float er0 = g_er_sorted[p];
        float er1 = g_er_sorted[p + 1];
        const float* hp0 = g_h + (size_t)s0 * OUT_CH;
        const float* hp1 = g_h + (size_t)s1 * OUT_CH;
        float a0 = hp0[lane], b0 = hp0[lane + 32];
        float a1 = hp1[lane], b1 = hp1[lane + 32];
        float w0 = __expf(leaky(el + er0));
        float w1 = __expf(leaky(el + er1));
        wsum += w0 + w1;
        acc0 = fmaf(w0, a0, acc0);
        acc1 = fmaf(w0, b0, acc1);
        acc0 = fmaf(w1, a1, acc0);
        acc1 = fmaf(w1, b1, acc1);
    }
    if (p < end) {
        int   s0  = g_src_sorted[p];
        float er0 = g_er_sorted[p];
        float w0 = __expf(leaky(el + er0));
        const float* hp0 = g_h + (size_t)s0 * OUT_CH;
        wsum += w0;
        acc0 = fmaf(w0, hp0[lane], acc0);
        acc1 = fmaf(w0, hp0[lane + 32], acc1);
    }
    float inv = 1.0f / (wsum + EPS_F);
    out[(size_t)node * OUT_CH + lane]      = acc0 * inv + bias[lane];
    out[(size_t)node * OUT_CH + 32 + lane] = acc1 * inv + bias[lane + 32];
}

// ---------------- launch ----------------
extern "C" void kernel_launch(void* const* d_in, const int* in_sizes, int n_in,
                              void* d_out, int out_size) {
    const float* x    = (const float*)d_in[0];
    const int*   ei   = (const int*)d_in[1];     // int32 (JAX x64 disabled)
    const float* W    = (const float*)d_in[2];
    const float* a_l  = (const float*)d_in[3];
    const float* a_r  = (const float*)d_in[4];
    const float* bias = (const float*)d_in[5];
    float* out = (float*)d_out;

    (void)in_sizes; (void)n_in; (void)out_size;

    init_kernel<<<(N_NODES + 255) / 256, 256>>>();
    gemm_kernel<<<(N_NODES + GEMM_ROWS - 1) / GEMM_ROWS, 128>>>(x, W, a_l, a_r);
    hist_kernel<<<(N_EDGES / 4 + 255) / 256, 256>>>(ei);
    scan_block_kernel<<<NUM_SCAN_BLOCKS, SCAN_BS>>>();
    scan_bsum_kernel<<<1, 128>>>();
    scan_add_kernel<<<(N_NODES + 255) / 256, 256>>>();
    scatter_kernel<<<(N_EDGES / 4 + 255) / 256, 256>>>(ei);
    {
        long long threads = (long long)N_NODES * 32;
        int blocks = (int)((threads + 255) / 256);
        msg_kernel<<<blocks, 256>>>(out, bias);
    }
}

// round 9
// speedup vs baseline: 1.0190x; 1.0190x over previous
#include <cuda_runtime.h>
#include <cuda_bf16.h>
#include <math_constants.h>

#define N_NODES 100000
#define N_EDGES 1600000
#define IN_CH   128
#define OUT_CH  64
#define NEG_SLOPE 0.2f
#define EPS_F 1e-10f

#define SCAN_BS 1024
#define NUM_SCAN_BLOCKS ((N_NODES + SCAN_BS - 1) / SCAN_BS)   // 98

// ---------------- scratch (no allocations allowed) ----------------
__device__ float g_h[(size_t)N_NODES * OUT_CH];   // 25.6 MB
__device__ float g_el[N_NODES];
__device__ float g_er[N_NODES];
__device__ int   g_deg[N_NODES];
__device__ int   g_fill[N_NODES];                 // preloaded with rowptr starts
__device__ int   g_rowptr[N_NODES + 1];
__device__ int   g_bsum[NUM_SCAN_BLOCKS];
__device__ int2  g_edge_sorted[N_EDGES];          // (src, er-bits) 12.8 MB

__device__ __forceinline__ float leaky(float v) {
    return v > 0.0f ? v : NEG_SLOPE * v;
}

// ---------------- K0: zero deg ----------------
__global__ void init_kernel() {
    int i = blockIdx.x * blockDim.x + threadIdx.x;
    if (i < N_NODES) g_deg[i] = 0;
}

// ================= K1: split-bf16 tensor-core GEMM + fused elr =================
// h = x @ W^T computed as xh*Wh + xl*Wh + xh*Wl  (fp32 accum, mma.sync m16n8k16)
// block: 256 threads = 8 warps; 128 rows x 64 cols per block; K=128 fully resident.
#define GEMM_ROWS 128
#define XS_STRIDE 136                       // bf16 elems per row (272B, conflict-free)
#define XS_ELEMS  (GEMM_ROWS * XS_STRIDE)   // 17408
#define WS_ELEMS  (OUT_CH * XS_STRIDE)      // 8704
#define GEMM_SMEM_BYTES ((2 * XS_ELEMS + 2 * WS_ELEMS) * 2)   // 104448

__device__ __forceinline__ void store_split4(__nv_bfloat16* hi, __nv_bfloat16* lo,
                                             int idx, float4 v) {
    float f[4] = {v.x, v.y, v.z, v.w};
    unsigned hb[4], lb[4];
#pragma unroll
    for (int j = 0; j < 4; j++) {
        __nv_bfloat16 h = __float2bfloat16_rn(f[j]);
        float hf = __bfloat162float(h);
        __nv_bfloat16 l = __float2bfloat16_rn(f[j] - hf);
        hb[j] = (unsigned)__bfloat16_as_ushort(h);
        lb[j] = (unsigned)__bfloat16_as_ushort(l);
    }
    unsigned* ph = reinterpret_cast<unsigned*>(hi + idx);
    unsigned* pl = reinterpret_cast<unsigned*>(lo + idx);
    ph[0] = hb[0] | (hb[1] << 16);
    ph[1] = hb[2] | (hb[3] << 16);
    pl[0] = lb[0] | (lb[1] << 16);
    pl[1] = lb[2] | (lb[3] << 16);
}

__device__ __forceinline__ void mma16816(float d[4], const unsigned a[4], const unsigned b[2]) {
    asm volatile(
        "mma.sync.aligned.m16n8k16.row.col.f32.bf16.bf16.f32 "
        "{%0,%1,%2,%3}, {%4,%5,%6,%7}, {%8,%9}, {%0,%1,%2,%3};\n"
        : "+f"(d[0]), "+f"(d[1]), "+f"(d[2]), "+f"(d[3])
        : "r"(a[0]), "r"(a[1]), "r"(a[2]), "r"(a[3]), "r"(b[0]), "r"(b[1]));
}

__device__ __forceinline__ void gemm_pass(const __nv_bfloat16* xa, const __nv_bfloat16* wb,
                                          int wm, int wn, int g, int tig,
                                          float d[2][4][4]) {
#pragma unroll
    for (int ks = 0; ks < 8; ks++) {
        int k0 = ks * 16;
        unsigned a[2][4];
        unsigned b[4][2];
#pragma unroll
        for (int mi = 0; mi < 2; mi++) {
            int rb = wm * 32 + mi * 16;
            a[mi][0] = *reinterpret_cast<const unsigned*>(xa + (rb + g)     * XS_STRIDE + k0 + tig * 2);
            a[mi][1] = *reinterpret_cast<const unsigned*>(xa + (rb + g + 8) * XS_STRIDE + k0 + tig * 2);
            a[mi][2] = *reinterpret_cast<const unsigned*>(xa + (rb + g)     * XS_STRIDE + k0 + tig * 2 + 8);
            a[mi][3] = *reinterpret_cast<const unsigned*>(xa + (rb + g + 8) * XS_STRIDE + k0 + tig * 2 + 8);
        }
#pragma unroll
        for (int ni = 0; ni < 4; ni++) {
            int oc = wn * 32 + ni * 8 + g;
            b[ni][0] = *reinterpret_cast<const unsigned*>(wb + oc * XS_STRIDE + k0 + tig * 2);
            b[ni][1] = *reinterpret_cast<const unsigned*>(wb + oc * XS_STRIDE + k0 + tig * 2 + 8);
        }
#pragma unroll
        for (int mi = 0; mi < 2; mi++)
#pragma unroll
            for (int ni = 0; ni < 4; ni++)
                mma16816(d[mi][ni], a[mi], b[ni]);
    }
}

__global__ __launch_bounds__(256) void gemm_kernel(const float* __restrict__ x,
                                                   const float* __restrict__ W,
                                                   const float* __restrict__ a_l,
                                                   const float* __restrict__ a_r) {
    extern __shared__ __align__(16) char dynsmem[];
    __nv_bfloat16* xs_hi = reinterpret_cast<__nv_bfloat16*>(dynsmem);
    __nv_bfloat16* xs_lo = xs_hi + XS_ELEMS;
    __nv_bfloat16* ws_hi = xs_lo + XS_ELEMS;
    __nv_bfloat16* ws_lo = ws_hi + WS_ELEMS;
    __shared__ float s_el[GEMM_ROWS];
    __shared__ float s_er[GEMM_ROWS];

    int tid = threadIdx.x;
    int row0 = blockIdx.x * GEMM_ROWS;

    if (tid < GEMM_ROWS) { s_el[tid] = 0.0f; s_er[tid] = 0.0f; }

    // stage x (split into hi/lo bf16)
    for (int i = tid; i < GEMM_ROWS * (IN_CH / 4); i += 256) {
        int r  = i >> 5;
        int c4 = (i & 31) << 2;
        int row = row0 + r;
        float4 v = make_float4(0.f, 0.f, 0.f, 0.f);
        if (row < N_NODES) v = *reinterpret_cast<const float4*>(x + (size_t)row * IN_CH + c4);
        store_split4(xs_hi, xs_lo, r * XS_STRIDE + c4, v);
    }
    // stage W (64 x 128)
    for (int i = tid; i < OUT_CH * (IN_CH / 4); i += 256) {
        int r  = i >> 5;
        int c4 = (i & 31) << 2;
        float4 v = *reinterpret_cast<const float4*>(W + (size_t)r * IN_CH + c4);
        store_split4(ws_hi, ws_lo, r * XS_STRIDE + c4, v);
    }
    __syncthreads();

    int lane = tid & 31, wid = tid >> 5;
    int wm = wid & 3, wn = wid >> 2;
    int g = lane >> 2, tig = lane & 3;

    float d[2][4][4];
#pragma unroll
    for (int mi = 0; mi < 2; mi++)
#pragma unroll
        for (int ni = 0; ni < 4; ni++)
#pragma unroll
            for (int q = 0; q < 4; q++) d[mi][ni][q] = 0.0f;

    gemm_pass(xs_hi, ws_hi, wm, wn, g, tig, d);
    gemm_pass(xs_lo, ws_hi, wm, wn, g, tig, d);
    gemm_pass(xs_hi, ws_lo, wm, wn, g, tig, d);

    // preload attention vectors for this thread's columns
    float alv[4][2], arv[4][2];
#pragma unroll
    for (int ni = 0; ni < 4; ni++) {
        int c = wn * 32 + ni * 8 + tig * 2;
        alv[ni][0] = a_l[c];     alv[ni][1] = a_l[c + 1];
        arv[ni][0] = a_r[c];     arv[ni][1] = a_r[c + 1];
    }

#pragma unroll
    for (int mi = 0; mi < 2; mi++) {
        int r1 = wm * 32 + mi * 16 + g;
        int r2 = r1 + 8;
        int grow1 = row0 + r1, grow2 = row0 + r2;
        float sl1 = 0.f, sr1 = 0.f, sl2 = 0.f, sr2 = 0.f;
#pragma unroll
        for (int ni = 0; ni < 4; ni++) {
            int c = wn * 32 + ni * 8 + tig * 2;
            float d0 = d[mi][ni][0], d1 = d[mi][ni][1];
            float d2 = d[mi][ni][2], d3 = d[mi][ni][3];
            sl1 = fmaf(d0, alv[ni][0], fmaf(d1, alv[ni][1], sl1));
            sr1 = fmaf(d0, arv[ni][0], fmaf(d1, arv[ni][1], sr1));
            sl2 = fmaf(d2, alv[ni][0], fmaf(d3, alv[ni][1], sl2));
            sr2 = fmaf(d2, arv[ni][0], fmaf(d3, arv[ni][1], sr2));
            if (grow1 < N_NODES)
                *reinterpret_cast<float2*>(g_h + (size_t)grow1 * OUT_CH + c) = make_float2(d0, d1);
            if (grow2 < N_NODES)
                *reinterpret_cast<float2*>(g_h + (size_t)grow2 * OUT_CH + c) = make_float2(d2, d3);
        }
        // reduce over the 4 lanes of the quad (tig)
#pragma unroll
        for (int m = 1; m < 4; m <<= 1) {
            sl1 += __shfl_xor_sync(0xFFFFFFFFu, sl1, m);
            sr1 += __shfl_xor_sync(0xFFFFFFFFu, sr1, m);
            sl2 += __shfl_xor_sync(0xFFFFFFFFu, sl2, m);
            sr2 += __shfl_xor_sync(0xFFFFFFFFu, sr2, m);
        }
        if (tig == 0) {
            atomicAdd(&s_el[r1], sl1); atomicAdd(&s_er[r1], sr1);
            atomicAdd(&s_el[r2], sl2); atomicAdd(&s_er[r2], sr2);
        }
    }
    __syncthreads();
    if (tid < GEMM_ROWS) {
        int row = row0 + tid;
        if (row < N_NODES) { g_el[row] = s_el[tid]; g_er[row] = s_er[tid]; }
    }
}

// ---------------- K2: histogram of dst (4 edges/thread, int4) ----------------
__global__ void hist_kernel(const int* __restrict__ ei) {
    int t = blockIdx.x * blockDim.x + threadIdx.x;
    int e4 = t * 4;
    if (e4 >= N_EDGES) return;
    int4 d = *reinterpret_cast<const int4*>(ei + N_EDGES + e4);
    atomicAdd(&g_deg[d.x], 1);
    atomicAdd(&g_deg[d.y], 1);
    atomicAdd(&g_deg[d.z], 1);
    atomicAdd(&g_deg[d.w], 1);
}

// ---------------- K3a: per-block inclusive scan of deg ----------------
__global__ void scan_block_kernel() {
    __shared__ int warp_sums[32];
    int i = blockIdx.x * SCAN_BS + threadIdx.x;
    int lane = threadIdx.x & 31, wid = threadIdx.x >> 5;
    int v = (i < N_NODES) ? g_deg[i] : 0;
    int s = v;
#pragma unroll
    for (int o = 1; o < 32; o <<= 1) {
        int t = __shfl_up_sync(0xFFFFFFFFu, s, o);
        if (lane >= o) s += t;
    }
    if (lane == 31) warp_sums[wid] = s;
    __syncthreads();
    if (wid == 0) {
        int ws = warp_sums[lane];
#pragma unroll
        for (int o = 1; o < 32; o <<= 1) {
            int t = __shfl_up_sync(0xFFFFFFFFu, ws, o);
            if (lane >= o) ws += t;
        }
        warp_sums[lane] = ws;
    }
    __syncthreads();
    int incl = s + (wid > 0 ? warp_sums[wid - 1] : 0);
    if (i < N_NODES) g_rowptr[i + 1] = incl;
    if (threadIdx.x == SCAN_BS - 1) g_bsum[blockIdx.x] = incl;
}

// ---------------- K3b: exclusive scan of block sums (1 block) ----------------
__global__ void scan_bsum_kernel() {
    __shared__ int sh[NUM_SCAN_BLOCKS];
    int t = threadIdx.x;
    if (t < NUM_SCAN_BLOCKS) sh[t] = g_bsum[t];
    __syncthreads();
    if (t == 0) {
        int run = 0;
        for (int b = 0; b < NUM_SCAN_BLOCKS; b++) {
            int v = sh[b];
            sh[b] = run;
            run += v;
        }
    }
    __syncthreads();
    if (t < NUM_SCAN_BLOCKS) g_bsum[t] = sh[t];
}

// ---------------- K3c: finalize rowptr AND preload g_fill with starts ----------------
__global__ void scan_add_kernel() {
    int i = blockIdx.x * blockDim.x + threadIdx.x;
    if (i < N_NODES) {
        int v = g_rowptr[i + 1] + g_bsum[i >> 10];
        g_rowptr[i + 1] = v;
        if (i + 1 < N_NODES) g_fill[i + 1] = v;   // start of node i+1
    }
    if (i == 0) { g_rowptr[0] = 0; g_fill[0] = 0; }
}

// ---------------- K4: scatter (src, er) packed into CSR order ----------------
__global__ void scatter_kernel(const int* __restrict__ ei) {
    int t = blockIdx.x * blockDim.x + threadIdx.x;
    int e4 = t * 4;
    if (e4 >= N_EDGES) return;
    int4 s = *reinterpret_cast<const int4*>(ei + e4);
    int4 d = *reinterpret_cast<const int4*>(ei + N_EDGES + e4);
#pragma unroll
    for (int j = 0; j < 4; j++) {
        int src = (j == 0) ? s.x : (j == 1) ? s.y : (j == 2) ? s.z : s.w;
        int dst = (j == 0) ? d.x : (j == 1) ? d.y : (j == 2) ? d.z : d.w;
        int pos = atomicAdd(&g_fill[dst], 1);
        g_edge_sorted[pos] = make_int2(src, __float_as_int(g_er[src]));
    }
}

// ---------------- K5: softmax + gather, 2 warps per node, unroll x4 ----------------
// NOTE: max-shift dropped; differs from reference by eps*(e^max-1)/sum ~ 3e-8.
__global__ void msg_kernel(float* __restrict__ out, const float* __restrict__ bias) {
    int gtid = blockIdx.x * blockDim.x + threadIdx.x;
    int w = gtid >> 5;
    int node = w >> 1;
    if (node >= N_NODES) return;
    int half = w & 1;
    int lane = gtid & 31;
    int chan = half * 32 + lane;
    int p   = g_rowptr[node];
    int end = g_rowptr[node + 1];
    float el = g_el[node];
    float acc = 0.0f, wsum = 0.0f;
    for (; p + 4 <= end; p += 4) {
        int2 e0 = g_edge_sorted[p];
        int2 e1 = g_edge_sorted[p + 1];
        int2 e2 = g_edge_sorted[p + 2];
        int2 e3 = g_edge_sorted[p + 3];
        float h0 = g_h[(size_t)e0.x * OUT_CH + chan];
        float h1 = g_h[(size_t)e1.x * OUT_CH + chan];
        float h2 = g_h[(size_t)e2.x * OUT_CH + chan];
        float h3 = g_h[(size_t)e3.x * OUT_CH + chan];
        float w0 = __expf(leaky(el + __int_as_float(e0.y)));
        float w1 = __expf(leaky(el + __int_as_float(e1.y)));
        float w2 = __expf(leaky(el + __int_as_float(e2.y)));
        float w3 = __expf(leaky(el + __int_as_float(e3.y)));
        wsum += (w0 + w1) + (w2 + w3);
        acc = fmaf(w0, h0, acc);
        acc = fmaf(w1, h1, acc);
        acc = fmaf(w2, h2, acc);
        acc = fmaf(w3, h3, acc);
    }
    for (; p < end; p++) {
        int2 e0 = g_edge_sorted[p];
        float w0 = __expf(leaky(el + __int_as_float(e0.y)));
        wsum += w0;
        acc = fmaf(w0, g_h[(size_t)e0.x * OUT_CH + chan], acc);
    }
    out[(size_t)node * OUT_CH + chan] = acc / (wsum + EPS_F) + bias[chan];
}

// ---------------- launch ----------------
extern "C" void kernel_launch(void* const* d_in, const int* in_sizes, int n_in,
                              void* d_out, int out_size) {
    const float* x    = (const float*)d_in[0];
    const int*   ei   = (const int*)d_in[1];     // int32 (JAX x64 disabled)
    const float* W    = (const float*)d_in[2];
    const float* a_l  = (const float*)d_in[3];
    const float* a_r  = (const float*)d_in[4];
    const float* bias = (const float*)d_in[5];
    float* out = (float*)d_out;

    (void)in_sizes; (void)n_in; (void)out_size;

    cudaFuncSetAttribute(gemm_kernel, cudaFuncAttributeMaxDynamicSharedMemorySize,
                         GEMM_SMEM_BYTES);

    init_kernel<<<(N_NODES + 255) / 256, 256>>>();
    gemm_kernel<<<(N_NODES + GEMM_ROWS - 1) / GEMM_ROWS, 256, GEMM_SMEM_BYTES>>>(x, W, a_l, a_r);
    hist_kernel<<<(N_EDGES / 4 + 255) / 256, 256>>>(ei);
    scan_block_kernel<<<NUM_SCAN_BLOCKS, SCAN_BS>>>();
    scan_bsum_kernel<<<1, 128>>>();
    scan_add_kernel<<<(N_NODES + 255) / 256, 256>>>();
    scatter_kernel<<<(N_EDGES / 4 + 255) / 256, 256>>>(ei);
    {
        long long threads = (long long)N_NODES * 64;   // 2 warps per node
        int blocks = (int)((threads + 255) / 256);
        msg_kernel<<<blocks, 256>>>(out, bias);
    }
}